// round 11
// baseline (speedup 1.0000x reference)
#include <cuda_runtime.h>
#include <cuda_bf16.h>
#include <cuda_fp16.h>
#include <math.h>
#include <stdint.h>

#define BATCH 64
#define SEQ   512
#define HSZ   1024
#define N4    4096
#define MTOT  (BATCH * SEQ)   // 32768
#define NCTA  128

// ============================ device scratch ================================
__device__ __align__(128) __nv_bfloat16 g_WiT_hi[(size_t)N4 * HSZ]; // [n'][k]
__device__ __align__(128) __nv_bfloat16 g_WiT_lo[(size_t)N4 * HSZ];
__device__ __align__(128) __half g_WhT_h[(size_t)N4 * HSZ];         // fp16 hi
__device__ __align__(128) __half g_WhT_l[(size_t)N4 * HSZ];         // fp16 (lo*2048)
__device__ __align__(128) __nv_bfloat16 g_x_hi[(size_t)MTOT * HSZ]; // [b*512+t][k]
__device__ __align__(128) __nv_bfloat16 g_x_lo[(size_t)MTOT * HSZ];
__device__ __align__(128) float g_bias_p[N4];
__device__ __align__(128) float g_xp[(size_t)MTOT * N4];            // [t*64+b][n']
__device__ __align__(128) __half g_h16[2][BATCH * HSZ];
__device__ __align__(128) float g_hf[BATCH * HSZ];
__device__ __align__(128) float g_c[BATCH * HSZ];
__device__ __align__(128) unsigned g_flags[NCTA * 8];               // 32B-padded epochs

// ============================ PTX helpers ===================================
__device__ __forceinline__ uint32_t smem_u32(const void* p) {
    uint32_t a;
    asm("{ .reg .u64 t; cvta.to.shared.u64 t, %1; cvt.u32.u64 %0, t; }" : "=r"(a) : "l"(p));
    return a;
}
__device__ __forceinline__ void ldm4(uint32_t addr, uint32_t r[4]) {
    asm volatile("ldmatrix.sync.aligned.m8n8.x4.shared.b16 {%0,%1,%2,%3}, [%4];"
                 : "=r"(r[0]), "=r"(r[1]), "=r"(r[2]), "=r"(r[3]) : "r"(addr));
}
__device__ __forceinline__ void hmma_bf16(float c[4], const uint32_t a[4], uint32_t b0, uint32_t b1) {
    asm volatile("mma.sync.aligned.m16n8k16.row.col.f32.bf16.bf16.f32 "
                 "{%0,%1,%2,%3},{%4,%5,%6,%7},{%8,%9},{%0,%1,%2,%3};"
                 : "+f"(c[0]), "+f"(c[1]), "+f"(c[2]), "+f"(c[3])
                 : "r"(a[0]), "r"(a[1]), "r"(a[2]), "r"(a[3]), "r"(b0), "r"(b1));
}
__device__ __forceinline__ void hmma_f16(float c[4], const uint32_t a[4], uint32_t b0, uint32_t b1) {
    asm volatile("mma.sync.aligned.m16n8k16.row.col.f32.f16.f16.f32 "
                 "{%0,%1,%2,%3},{%4,%5,%6,%7},{%8,%9},{%0,%1,%2,%3};"
                 : "+f"(c[0]), "+f"(c[1]), "+f"(c[2]), "+f"(c[3])
                 : "r"(a[0]), "r"(a[1]), "r"(a[2]), "r"(a[3]), "r"(b0), "r"(b1));
}
#define CP16(d, s)  asm volatile("cp.async.cg.shared.global [%0], [%1], 16;" ::"r"(d), "l"(s))
#define CPCOMMIT()  asm volatile("cp.async.commit_group;" ::: "memory")
#define CPWAIT2()   asm volatile("cp.async.wait_group 2;" ::: "memory")
#define CPWAIT1()   asm volatile("cp.async.wait_group 1;" ::: "memory")
#define CPWAIT0()   asm volatile("cp.async.wait_group 0;" ::: "memory")

#define SROW 144      // 64 bf16 = 128B data + 16B pad (conflict-free ldmatrix)

// fast, saturation-safe activations (approx err ~2^-22, << 5e-5 floor)
__device__ __forceinline__ float fsig(float x) {
    return __fdividef(1.0f, 1.0f + __expf(-x));
}
__device__ __forceinline__ float ftanh(float x) {
    return 1.0f - __fdividef(2.0f, __expf(2.0f * x) + 1.0f);
}

// ============================== pack weights ================================
__global__ void pack_w(const float* __restrict__ wii, const float* __restrict__ wif,
                       const float* __restrict__ wig, const float* __restrict__ wio,
                       const float* __restrict__ whi, const float* __restrict__ whf,
                       const float* __restrict__ whg, const float* __restrict__ who)
{
    __shared__ float tile[32][33];
    const float* srcs[8] = {wii, wif, wig, wio, whi, whf, whg, who};
    int z = blockIdx.z;
    const float* src = srcs[z];
    int g = z & 3;
    int k0 = blockIdx.x * 32, hc0 = blockIdx.y * 32;
    int tx = threadIdx.x, ty = threadIdx.y;   // (32, 8)
#pragma unroll
    for (int i = 0; i < 4; i++) {
        int k = k0 + ty + i * 8;
        tile[ty + i * 8][tx] = src[(size_t)k * HSZ + hc0 + tx];
    }
    __syncthreads();
#pragma unroll
    for (int i = 0; i < 4; i++) {
        int r = ty + i * 8;
        size_t np = (size_t)(hc0 + r) * 4 + g;
        float v = tile[tx][r];
        if (z < 4) {
            __nv_bfloat16 hi = __float2bfloat16(v);
            float lo = v - __bfloat162float(hi);
            g_WiT_hi[np * HSZ + k0 + tx] = hi;
            g_WiT_lo[np * HSZ + k0 + tx] = __float2bfloat16(lo);
        } else {
            __half hi = __float2half_rn(v);
            float lo = (v - __half2float(hi)) * 2048.0f;
            g_WhT_h[np * HSZ + k0 + tx] = hi;
            g_WhT_l[np * HSZ + k0 + tx] = __float2half_rn(lo);
        }
    }
}

// ======================== init state + packed bias ==========================
__global__ void init_state(const float* __restrict__ bii, const float* __restrict__ bhi,
                           const float* __restrict__ bif, const float* __restrict__ bhf,
                           const float* __restrict__ big, const float* __restrict__ bhg,
                           const float* __restrict__ bio, const float* __restrict__ bho)
{
    int i = blockIdx.x * blockDim.x + threadIdx.x;
    if (i < NCTA * 8) g_flags[i] = 0u;
    if (i < BATCH * HSZ) {
        __half z = __float2half_rn(0.f);
        g_h16[0][i] = z; g_h16[1][i] = z;
    }
    if (i < N4) {
        int hc = i >> 2, g = i & 3;
        const float* bi[4] = {bii, bif, big, bio};
        const float* bh[4] = {bhi, bhf, bhg, bho};
        g_bias_p[i] = bi[g][hc] + bh[g][hc];
    }
}

// =========================== x -> bf16 hi/lo split ==========================
__global__ void conv_x(const float* __restrict__ x)
{
    size_t i = (size_t)blockIdx.x * blockDim.x + threadIdx.x;   // float4 index
    float4 v = ((const float4*)x)[i];
    __nv_bfloat16 h0 = __float2bfloat16(v.x);
    __nv_bfloat16 h1 = __float2bfloat16(v.y);
    __nv_bfloat16 h2 = __float2bfloat16(v.z);
    __nv_bfloat16 h3 = __float2bfloat16(v.w);
    __nv_bfloat16 l0 = __float2bfloat16(v.x - __bfloat162float(h0));
    __nv_bfloat16 l1 = __float2bfloat16(v.y - __bfloat162float(h1));
    __nv_bfloat16 l2 = __float2bfloat16(v.z - __bfloat162float(h2));
    __nv_bfloat16 l3 = __float2bfloat16(v.w - __bfloat162float(h3));
    ((__nv_bfloat162*)g_x_hi)[i * 2]     = __halves2bfloat162(h0, h1);
    ((__nv_bfloat162*)g_x_hi)[i * 2 + 1] = __halves2bfloat162(h2, h3);
    ((__nv_bfloat162*)g_x_lo)[i * 2]     = __halves2bfloat162(l0, l1);
    ((__nv_bfloat162*)g_x_lo)[i * 2 + 1] = __halves2bfloat162(l2, l3);
}

// ========================= xproj GEMM (HMMA, bf16 3-term) ===================
#define XSTG 73728
__global__ void __launch_bounds__(256, 1) xproj_mma()
{
    extern __shared__ __align__(128) char smem[];
    const uint32_t sb = smem_u32(smem);
    const int tid = threadIdx.x;
    const int n0 = blockIdx.x * 128, m0 = blockIdx.y * 128;
    const int wid = tid >> 5, l = tid & 31;
    const int wm = wid >> 1, wn = wid & 1;    // 4 x 2 warps

    auto load_chunk = [&](int c, int st) {
        uint32_t base = sb + (uint32_t)st * XSTG;
        int ko = c * 64;
#pragma unroll
        for (int j = 0; j < 4; j++) {
            int cid = tid * 4 + j;          // 0..1023
            int row = cid >> 3, kc = cid & 7;
            uint32_t doff = row * SROW + kc * 16;
            CP16(base + doff,          g_x_hi  + (size_t)(m0 + row) * HSZ + ko + kc * 8);
            CP16(base + 18432 + doff,  g_x_lo  + (size_t)(m0 + row) * HSZ + ko + kc * 8);
            CP16(base + 36864 + doff,  g_WiT_hi + (size_t)(n0 + row) * HSZ + ko + kc * 8);
            CP16(base + 55296 + doff,  g_WiT_lo + (size_t)(n0 + row) * HSZ + ko + kc * 8);
        }
        CPCOMMIT();
    };

    float acc[2][8][4];
#pragma unroll
    for (int i = 0; i < 2; i++)
#pragma unroll
        for (int j = 0; j < 8; j++)
#pragma unroll
            for (int k = 0; k < 4; k++) acc[i][j][k] = 0.f;

    const uint32_t aoff = (wm * 32 + (l & 15)) * SROW + (l >> 4) * 16;
    const uint32_t boff = 36864u + (wn * 64 + (l & 15)) * SROW + (l >> 4) * 16;

    load_chunk(0, 0);
    load_chunk(1, 1);

    for (int c = 0; c < 16; c++) {
        if (c < 15) { CPWAIT1(); } else { CPWAIT0(); }
        __syncthreads();
        if (c + 2 < 16) load_chunk(c + 2, (c + 2) % 3);
        uint32_t base = sb + (uint32_t)(c % 3) * XSTG;
#pragma unroll
        for (int ks = 0; ks < 4; ks++) {
            uint32_t aO = base + aoff + ks * 32;
            uint32_t bO = base + boff + ks * 32;
            uint32_t ah0[4], ah1[4], al0[4], al1[4];
            ldm4(aO,              ah0);
            ldm4(aO + 16 * SROW,  ah1);
            ldm4(aO + 18432,             al0);
            ldm4(aO + 18432 + 16 * SROW, al1);
#pragma unroll
            for (int nh = 0; nh < 4; nh++) {
                uint32_t bh[4], bl[4];
                ldm4(bO + nh * 16 * SROW,         bh);
                ldm4(bO + nh * 16 * SROW + 18432, bl);
                int nb = nh * 2;
                hmma_bf16(acc[0][nb],     ah0, bh[0], bh[2]);
                hmma_bf16(acc[0][nb + 1], ah0, bh[1], bh[3]);
                hmma_bf16(acc[1][nb],     ah1, bh[0], bh[2]);
                hmma_bf16(acc[1][nb + 1], ah1, bh[1], bh[3]);
                hmma_bf16(acc[0][nb],     ah0, bl[0], bl[2]);
                hmma_bf16(acc[0][nb + 1], ah0, bl[1], bl[3]);
                hmma_bf16(acc[1][nb],     ah1, bl[0], bl[2]);
                hmma_bf16(acc[1][nb + 1], ah1, bl[1], bl[3]);
                hmma_bf16(acc[0][nb],     al0, bh[0], bh[2]);
                hmma_bf16(acc[0][nb + 1], al0, bh[1], bh[3]);
                hmma_bf16(acc[1][nb],     al1, bh[0], bh[2]);
                hmma_bf16(acc[1][nb + 1], al1, bh[1], bh[3]);
            }
        }
    }

    // epilogue: bias + store to g_xp[(t*64+b)][n'],  m = b*512 + t
#pragma unroll
    for (int mi = 0; mi < 2; mi++) {
#pragma unroll
        for (int nb = 0; nb < 8; nb++) {
            int row = m0 + wm * 32 + mi * 16 + (l >> 2);
            int col = n0 + wn * 64 + nb * 8 + 2 * (l & 3);
            float2 bv = *(const float2*)&g_bias_p[col];
            size_t r0 = ((size_t)(row & 511) * BATCH + (row >> 9)) * N4;
            *(float2*)&g_xp[r0 + col] = make_float2(acc[mi][nb][0] + bv.x,
                                                    acc[mi][nb][1] + bv.y);
            int row2 = row + 8;
            size_t r1 = ((size_t)(row2 & 511) * BATCH + (row2 >> 9)) * N4;
            *(float2*)&g_xp[r1 + col] = make_float2(acc[mi][nb][2] + bv.x,
                                                    acc[mi][nb][3] + bv.y);
        }
    }
}

// ==================== persistent recurrence (all 512 steps) =================
// 128 CTAs x 256 thr. CTA owns 32 n' rows. Wh (fp16 hi + lo*2048) resident in
// smem. Per step: stream h (single fp16) in 8 chunks of K=128 (4-stage, 3-ahead
// cp.async pipeline), 2-term HMMA, fused cell update. Step handoff via
// distributed per-CTA release/acquire flags (no atomics, no central barrier).
#define WROW2   2064                        // 1024 fp16 = 2048B + 16B pad
#define WLO_OFF (32 * WROW2)                // 66048
#define HOFF2   (2 * 32 * WROW2)            // 132096
#define HROW2   272                         // 128 fp16 = 256B + 16B pad
#define HSTG2   (64 * HROW2)                // 17408
#define DSOFF2  (HOFF2 + 4 * HSTG2)         // 201728
#define PCOFF2  (DSOFF2 + 32 * 68 * 4)      // 210432
#define PSMEM2  (PCOFF2 + 512 * 4)          // 212480

__global__ void __launch_bounds__(256, 1) lstm_persist()
{
    extern __shared__ __align__(128) char smem[];
    const uint32_t sb = smem_u32(smem);
    const int tid = threadIdx.x;
    const int cta = blockIdx.x;
    const int n0 = cta * 32;
    const int wid = tid >> 5, l = tid & 31;
    const int wm = wid & 1, wn = wid >> 1;    // 2 m-halves x 4 n-quarters

    // ---- load resident W slice (hi & scaled-lo fp16), 128 KB ----
    for (int i = tid; i < 4096; i += 256) {
        int row = i >> 7, c16 = i & 127;
        uint32_t d = sb + row * WROW2 + c16 * 16;
        CP16(d,           g_WhT_h + (size_t)(n0 + row) * HSZ + c16 * 8);
        CP16(d + WLO_OFF, g_WhT_l + (size_t)(n0 + row) * HSZ + c16 * 8);
    }
    CPCOMMIT(); CPWAIT0();

    float* c_s = (float*)(smem + PCOFF2);
    float* Ds  = (float*)(smem + DSOFF2);
    for (int i = tid; i < 512; i += 256) c_s[i] = 0.f;
    __syncthreads();

    const uint32_t aoffh = sb + (wm * 16 + (l & 15)) * WROW2 + (l >> 4) * 16;
    const uint32_t aoffl = aoffh + WLO_OFF;
    const uint32_t boffr = (wn * 16 + (l & 15)) * HROW2 + (l >> 4) * 16;

    const int b = tid & 63, q = tid >> 6;     // cell ownership: (b, hc=2q, 2q+1)
    const int hcg0 = cta * 8 + 2 * q;

    for (int t = 0; t < SEQ; t++) {
        const __half* __restrict__ hin = g_h16[t & 1];

        // xp prefetch (independent of h_t) — overlaps flag-wait + fill
        const float* xprow = g_xp + ((size_t)t * BATCH + b) * N4 + n0 + q * 8;
        float4 xpA = *(const float4*)(xprow);
        float4 xpB = *(const float4*)(xprow + 4);

        // distributed flag barrier: wait until every CTA published h_t
        if (t > 0) {
            if (tid < NCTA) {
                unsigned f;
                do {
                    asm volatile("ld.global.acquire.gpu.u32 %0, [%1];"
                                 : "=r"(f) : "l"(g_flags + tid * 8) : "memory");
                } while (f < (unsigned)t);
            }
            __syncthreads();
        }

        auto load_h = [&](int c, int st) {
            uint32_t base = sb + HOFF2 + (uint32_t)st * HSTG2;
            int ko = c * 128;
#pragma unroll
            for (int j = 0; j < 4; j++) {
                int cid = tid * 4 + j;        // 0..1023
                int row = cid >> 4, kc = cid & 15;
                CP16(base + row * HROW2 + kc * 16, hin + (size_t)row * HSZ + ko + kc * 8);
            }
            CPCOMMIT();
        };

        float accH[2][4], accL[2][4];
#pragma unroll
        for (int i = 0; i < 2; i++)
#pragma unroll
            for (int k = 0; k < 4; k++) { accH[i][k] = 0.f; accL[i][k] = 0.f; }

        load_h(0, 0);
        load_h(1, 1);
        load_h(2, 2);

#pragma unroll 1
        for (int c = 0; c < 8; c++) {
            if (c <= 5) { CPWAIT2(); } else if (c == 6) { CPWAIT1(); } else { CPWAIT0(); }
            __syncthreads();                      // data ready; prev chunk fully consumed
            if (c + 3 < 8) load_h(c + 3, (c + 3) & 3);
            uint32_t wbase = c * 256;             // byte offset into W row (K-major)
            uint32_t hb = sb + HOFF2 + (uint32_t)(c & 3) * HSTG2 + boffr;
#pragma unroll
            for (int ks = 0; ks < 8; ks++) {
                uint32_t ah[4], al[4], bh[4];
                ldm4(aoffh + wbase + ks * 32, ah);
                ldm4(aoffl + wbase + ks * 32, al);
                ldm4(hb + ks * 32, bh);
                hmma_f16(accH[0], ah, bh[0], bh[2]);
                hmma_f16(accH[1], ah, bh[1], bh[3]);
                hmma_f16(accL[0], al, bh[0], bh[2]);
                hmma_f16(accL[1], al, bh[1], bh[3]);
            }
        }

        // D [32 n'][64 b] -> smem (combine lo term)
        {
            int r = wm * 16 + (l >> 2);
#pragma unroll
            for (int nb = 0; nb < 2; nb++) {
                int col = wn * 16 + nb * 8 + 2 * (l & 3);
                const float s = 1.0f / 2048.0f;
                Ds[r * 68 + col]           = accH[nb][0] + accL[nb][0] * s;
                Ds[r * 68 + col + 1]       = accH[nb][1] + accL[nb][1] * s;
                Ds[(r + 8) * 68 + col]     = accH[nb][2] + accL[nb][2] * s;
                Ds[(r + 8) * 68 + col + 1] = accH[nb][3] + accL[nb][3] * s;
            }
        }
        __syncthreads();

        // fused cell update: this thread owns (b, hc=2q) and (b, hc=2q+1)
        float hv[2];
#pragma unroll
        for (int j = 0; j < 2; j++) {
            int hcl = 2 * q + j;
            float iv = Ds[(hcl * 4 + 0) * 68 + b];
            float fv = Ds[(hcl * 4 + 1) * 68 + b];
            float gv = Ds[(hcl * 4 + 2) * 68 + b];
            float ov = Ds[(hcl * 4 + 3) * 68 + b];
            float xi = j ? xpB.x : xpA.x;
            float xf = j ? xpB.y : xpA.y;
            float xg = j ? xpB.z : xpA.z;
            float xo = j ? xpB.w : xpA.w;
            float ig = fsig(iv + xi);
            float fg = fsig(fv + xf);
            float gg = ftanh(gv + xg);
            float og = fsig(ov + xo);
            int ci = b * 8 + hcl;
            float cnew = c_s[ci] * fg + ig * gg;
            c_s[ci] = cnew;
            hv[j] = og * ftanh(cnew);
        }
        {
            int idx = b * HSZ + hcg0;
            *(__half2*)(g_h16[(t + 1) & 1] + idx) =
                __halves2half2(__float2half_rn(hv[0]), __float2half_rn(hv[1]));
            if (t == SEQ - 1) {
                *(float2*)(g_hf + idx) = make_float2(hv[0], hv[1]);
                *(float2*)(g_c  + idx) = make_float2(c_s[b * 8 + 2 * q], c_s[b * 8 + 2 * q + 1]);
            }
        }

        // publish h_{t+1}: CG-style release-arrive (bar.sync orders all threads'
        // h stores before tid0's release store)
        __syncthreads();
        if (tid == 0) {
            asm volatile("st.global.release.gpu.u32 [%0], %1;"
                         ::"l"(g_flags + cta * 8), "r"((unsigned)(t + 1)) : "memory");
        }
    }
}

// ============================== output ======================================
__global__ void copy_out_kernel(float* __restrict__ out, int n)
{
    int i = blockIdx.x * blockDim.x + threadIdx.x;
    if (i >= n) return;
    if (i < BATCH * HSZ)          out[i] = g_hf[i];
    else if (i < 2 * BATCH * HSZ) out[i] = g_c[i - BATCH * HSZ];
    else                          out[i] = 0.0f;
}

// ============================== launcher ====================================
extern "C" void kernel_launch(void* const* d_in, const int* in_sizes, int n_in,
                              void* d_out, int out_size)
{
    const float* x   = (const float*)d_in[0];
    const float* wii = (const float*)d_in[1];
    const float* bii = (const float*)d_in[2];
    const float* whi = (const float*)d_in[3];
    const float* bhi = (const float*)d_in[4];
    const float* wif = (const float*)d_in[5];
    const float* bif = (const float*)d_in[6];
    const float* whf = (const float*)d_in[7];
    const float* bhf = (const float*)d_in[8];
    const float* wig = (const float*)d_in[9];
    const float* big = (const float*)d_in[10];
    const float* whg = (const float*)d_in[11];
    const float* bhg = (const float*)d_in[12];
    const float* wio = (const float*)d_in[13];
    const float* bio = (const float*)d_in[14];
    const float* who = (const float*)d_in[15];
    const float* bho = (const float*)d_in[16];
    (void)in_sizes; (void)n_in;

    static int configured = 0;
    if (!configured) {
        cudaFuncSetAttribute(xproj_mma,    cudaFuncAttributeMaxDynamicSharedMemorySize, 3 * XSTG);
        cudaFuncSetAttribute(lstm_persist, cudaFuncAttributeMaxDynamicSharedMemorySize, PSMEM2);
        configured = 1;
    }

    pack_w<<<dim3(32, 32, 8), dim3(32, 8)>>>(wii, wif, wig, wio, whi, whf, whg, who);
    init_state<<<(BATCH * HSZ + 255) / 256, 256>>>(bii, bhi, bif, bhf, big, bhg, bio, bho);
    conv_x<<<(MTOT * HSZ / 4 + 255) / 256, 256>>>(x);

    xproj_mma<<<dim3(32, 256), 256, 3 * XSTG>>>();

    lstm_persist<<<NCTA, 256, PSMEM2>>>();

    copy_out_kernel<<<(out_size + 255) / 256, 256>>>((float*)d_out, out_size);
}

// round 12
// speedup vs baseline: 1.0226x; 1.0226x over previous
#include <cuda_runtime.h>
#include <cuda_bf16.h>
#include <cuda_fp16.h>
#include <math.h>
#include <stdint.h>

#define BATCH 64
#define SEQ   512
#define HSZ   1024
#define N4    4096
#define MTOT  (BATCH * SEQ)   // 32768
#define NCTA  128

// ============================ device scratch ================================
__device__ __align__(128) __nv_bfloat16 g_WiT_hi[(size_t)N4 * HSZ]; // [n'][k]
__device__ __align__(128) __nv_bfloat16 g_WiT_lo[(size_t)N4 * HSZ];
__device__ __align__(128) __half g_WhT_h[(size_t)N4 * HSZ];         // fp16 hi
__device__ __align__(128) __half g_WhT_l[(size_t)N4 * HSZ];         // fp16 (lo*2048)
__device__ __align__(128) __nv_bfloat16 g_x_hi[(size_t)MTOT * HSZ]; // [b*512+t][k]
__device__ __align__(128) __nv_bfloat16 g_x_lo[(size_t)MTOT * HSZ];
__device__ __align__(128) float g_bias_p[N4];
__device__ __align__(128) float g_xp[(size_t)MTOT * N4];            // [t*64+b][n']
__device__ __align__(128) __half g_h16[2][BATCH * HSZ];
__device__ __align__(128) float g_hf[BATCH * HSZ];
__device__ __align__(128) float g_c[BATCH * HSZ];
__device__ __align__(128) unsigned g_flags[NCTA * 8];               // 32B-padded epochs

// ============================ PTX helpers ===================================
__device__ __forceinline__ uint32_t smem_u32(const void* p) {
    uint32_t a;
    asm("{ .reg .u64 t; cvta.to.shared.u64 t, %1; cvt.u32.u64 %0, t; }" : "=r"(a) : "l"(p));
    return a;
}
__device__ __forceinline__ void ldm4(uint32_t addr, uint32_t r[4]) {
    asm volatile("ldmatrix.sync.aligned.m8n8.x4.shared.b16 {%0,%1,%2,%3}, [%4];"
                 : "=r"(r[0]), "=r"(r[1]), "=r"(r[2]), "=r"(r[3]) : "r"(addr));
}
__device__ __forceinline__ void hmma_bf16(float c[4], const uint32_t a[4], uint32_t b0, uint32_t b1) {
    asm volatile("mma.sync.aligned.m16n8k16.row.col.f32.bf16.bf16.f32 "
                 "{%0,%1,%2,%3},{%4,%5,%6,%7},{%8,%9},{%0,%1,%2,%3};"
                 : "+f"(c[0]), "+f"(c[1]), "+f"(c[2]), "+f"(c[3])
                 : "r"(a[0]), "r"(a[1]), "r"(a[2]), "r"(a[3]), "r"(b0), "r"(b1));
}
__device__ __forceinline__ void hmma_f16(float c[4], const uint32_t a[4], uint32_t b0, uint32_t b1) {
    asm volatile("mma.sync.aligned.m16n8k16.row.col.f32.f16.f16.f32 "
                 "{%0,%1,%2,%3},{%4,%5,%6,%7},{%8,%9},{%0,%1,%2,%3};"
                 : "+f"(c[0]), "+f"(c[1]), "+f"(c[2]), "+f"(c[3])
                 : "r"(a[0]), "r"(a[1]), "r"(a[2]), "r"(a[3]), "r"(b0), "r"(b1));
}
#define CP16(d, s)  asm volatile("cp.async.cg.shared.global [%0], [%1], 16;" ::"r"(d), "l"(s))
#define CPCOMMIT()  asm volatile("cp.async.commit_group;" ::: "memory")
#define CPWAIT2()   asm volatile("cp.async.wait_group 2;" ::: "memory")
#define CPWAIT1()   asm volatile("cp.async.wait_group 1;" ::: "memory")
#define CPWAIT0()   asm volatile("cp.async.wait_group 0;" ::: "memory")

#define SROW 144      // 64 bf16 = 128B data + 16B pad (conflict-free ldmatrix)

// fast, saturation-safe activations (approx err ~2^-22, << 5e-5 floor)
__device__ __forceinline__ float fsig(float x) {
    return __fdividef(1.0f, 1.0f + __expf(-x));
}
__device__ __forceinline__ float ftanh(float x) {
    return 1.0f - __fdividef(2.0f, __expf(2.0f * x) + 1.0f);
}

// ============================== pack weights ================================
__global__ void pack_w(const float* __restrict__ wii, const float* __restrict__ wif,
                       const float* __restrict__ wig, const float* __restrict__ wio,
                       const float* __restrict__ whi, const float* __restrict__ whf,
                       const float* __restrict__ whg, const float* __restrict__ who)
{
    __shared__ float tile[32][33];
    const float* srcs[8] = {wii, wif, wig, wio, whi, whf, whg, who};
    int z = blockIdx.z;
    const float* src = srcs[z];
    int g = z & 3;
    int k0 = blockIdx.x * 32, hc0 = blockIdx.y * 32;
    int tx = threadIdx.x, ty = threadIdx.y;   // (32, 8)
#pragma unroll
    for (int i = 0; i < 4; i++) {
        int k = k0 + ty + i * 8;
        tile[ty + i * 8][tx] = src[(size_t)k * HSZ + hc0 + tx];
    }
    __syncthreads();
#pragma unroll
    for (int i = 0; i < 4; i++) {
        int r = ty + i * 8;
        size_t np = (size_t)(hc0 + r) * 4 + g;
        float v = tile[tx][r];
        if (z < 4) {
            __nv_bfloat16 hi = __float2bfloat16(v);
            float lo = v - __bfloat162float(hi);
            g_WiT_hi[np * HSZ + k0 + tx] = hi;
            g_WiT_lo[np * HSZ + k0 + tx] = __float2bfloat16(lo);
        } else {
            __half hi = __float2half_rn(v);
            float lo = (v - __half2float(hi)) * 2048.0f;
            g_WhT_h[np * HSZ + k0 + tx] = hi;
            g_WhT_l[np * HSZ + k0 + tx] = __float2half_rn(lo);
        }
    }
}

// ======================== init state + packed bias ==========================
__global__ void init_state(const float* __restrict__ bii, const float* __restrict__ bhi,
                           const float* __restrict__ bif, const float* __restrict__ bhf,
                           const float* __restrict__ big, const float* __restrict__ bhg,
                           const float* __restrict__ bio, const float* __restrict__ bho)
{
    int i = blockIdx.x * blockDim.x + threadIdx.x;
    if (i < NCTA * 8) g_flags[i] = 0u;
    if (i < BATCH * HSZ) {
        __half z = __float2half_rn(0.f);
        g_h16[0][i] = z; g_h16[1][i] = z;
    }
    if (i < N4) {
        int hc = i >> 2, g = i & 3;
        const float* bi[4] = {bii, bif, big, bio};
        const float* bh[4] = {bhi, bhf, bhg, bho};
        g_bias_p[i] = bi[g][hc] + bh[g][hc];
    }
}

// =========================== x -> bf16 hi/lo split ==========================
__global__ void conv_x(const float* __restrict__ x)
{
    size_t i = (size_t)blockIdx.x * blockDim.x + threadIdx.x;   // float4 index
    float4 v = ((const float4*)x)[i];
    __nv_bfloat16 h0 = __float2bfloat16(v.x);
    __nv_bfloat16 h1 = __float2bfloat16(v.y);
    __nv_bfloat16 h2 = __float2bfloat16(v.z);
    __nv_bfloat16 h3 = __float2bfloat16(v.w);
    __nv_bfloat16 l0 = __float2bfloat16(v.x - __bfloat162float(h0));
    __nv_bfloat16 l1 = __float2bfloat16(v.y - __bfloat162float(h1));
    __nv_bfloat16 l2 = __float2bfloat16(v.z - __bfloat162float(h2));
    __nv_bfloat16 l3 = __float2bfloat16(v.w - __bfloat162float(h3));
    ((__nv_bfloat162*)g_x_hi)[i * 2]     = __halves2bfloat162(h0, h1);
    ((__nv_bfloat162*)g_x_hi)[i * 2 + 1] = __halves2bfloat162(h2, h3);
    ((__nv_bfloat162*)g_x_lo)[i * 2]     = __halves2bfloat162(l0, l1);
    ((__nv_bfloat162*)g_x_lo)[i * 2 + 1] = __halves2bfloat162(l2, l3);
}

// ========================= xproj GEMM (HMMA, bf16 3-term) ===================
#define XSTG 73728
__global__ void __launch_bounds__(256, 1) xproj_mma()
{
    extern __shared__ __align__(128) char smem[];
    const uint32_t sb = smem_u32(smem);
    const int tid = threadIdx.x;
    const int n0 = blockIdx.x * 128, m0 = blockIdx.y * 128;
    const int wid = tid >> 5, l = tid & 31;
    const int wm = wid >> 1, wn = wid & 1;    // 4 x 2 warps

    auto load_chunk = [&](int c, int st) {
        uint32_t base = sb + (uint32_t)st * XSTG;
        int ko = c * 64;
#pragma unroll
        for (int j = 0; j < 4; j++) {
            int cid = tid * 4 + j;          // 0..1023
            int row = cid >> 3, kc = cid & 7;
            uint32_t doff = row * SROW + kc * 16;
            CP16(base + doff,          g_x_hi  + (size_t)(m0 + row) * HSZ + ko + kc * 8);
            CP16(base + 18432 + doff,  g_x_lo  + (size_t)(m0 + row) * HSZ + ko + kc * 8);
            CP16(base + 36864 + doff,  g_WiT_hi + (size_t)(n0 + row) * HSZ + ko + kc * 8);
            CP16(base + 55296 + doff,  g_WiT_lo + (size_t)(n0 + row) * HSZ + ko + kc * 8);
        }
        CPCOMMIT();
    };

    float acc[2][8][4];
#pragma unroll
    for (int i = 0; i < 2; i++)
#pragma unroll
        for (int j = 0; j < 8; j++)
#pragma unroll
            for (int k = 0; k < 4; k++) acc[i][j][k] = 0.f;

    const uint32_t aoff = (wm * 32 + (l & 15)) * SROW + (l >> 4) * 16;
    const uint32_t boff = 36864u + (wn * 64 + (l & 15)) * SROW + (l >> 4) * 16;

    load_chunk(0, 0);
    load_chunk(1, 1);

    for (int c = 0; c < 16; c++) {
        if (c < 15) { CPWAIT1(); } else { CPWAIT0(); }
        __syncthreads();
        if (c + 2 < 16) load_chunk(c + 2, (c + 2) % 3);
        uint32_t base = sb + (uint32_t)(c % 3) * XSTG;
#pragma unroll
        for (int ks = 0; ks < 4; ks++) {
            uint32_t aO = base + aoff + ks * 32;
            uint32_t bO = base + boff + ks * 32;
            uint32_t ah0[4], ah1[4], al0[4], al1[4];
            ldm4(aO,              ah0);
            ldm4(aO + 16 * SROW,  ah1);
            ldm4(aO + 18432,             al0);
            ldm4(aO + 18432 + 16 * SROW, al1);
#pragma unroll
            for (int nh = 0; nh < 4; nh++) {
                uint32_t bh[4], bl[4];
                ldm4(bO + nh * 16 * SROW,         bh);
                ldm4(bO + nh * 16 * SROW + 18432, bl);
                int nb = nh * 2;
                hmma_bf16(acc[0][nb],     ah0, bh[0], bh[2]);
                hmma_bf16(acc[0][nb + 1], ah0, bh[1], bh[3]);
                hmma_bf16(acc[1][nb],     ah1, bh[0], bh[2]);
                hmma_bf16(acc[1][nb + 1], ah1, bh[1], bh[3]);
                hmma_bf16(acc[0][nb],     ah0, bl[0], bl[2]);
                hmma_bf16(acc[0][nb + 1], ah0, bl[1], bl[3]);
                hmma_bf16(acc[1][nb],     ah1, bl[0], bl[2]);
                hmma_bf16(acc[1][nb + 1], ah1, bl[1], bl[3]);
                hmma_bf16(acc[0][nb],     al0, bh[0], bh[2]);
                hmma_bf16(acc[0][nb + 1], al0, bh[1], bh[3]);
                hmma_bf16(acc[1][nb],     al1, bh[0], bh[2]);
                hmma_bf16(acc[1][nb + 1], al1, bh[1], bh[3]);
            }
        }
    }

    // epilogue: bias + store to g_xp[(t*64+b)][n'],  m = b*512 + t
#pragma unroll
    for (int mi = 0; mi < 2; mi++) {
#pragma unroll
        for (int nb = 0; nb < 8; nb++) {
            int row = m0 + wm * 32 + mi * 16 + (l >> 2);
            int col = n0 + wn * 64 + nb * 8 + 2 * (l & 3);
            float2 bv = *(const float2*)&g_bias_p[col];
            size_t r0 = ((size_t)(row & 511) * BATCH + (row >> 9)) * N4;
            *(float2*)&g_xp[r0 + col] = make_float2(acc[mi][nb][0] + bv.x,
                                                    acc[mi][nb][1] + bv.y);
            int row2 = row + 8;
            size_t r1 = ((size_t)(row2 & 511) * BATCH + (row2 >> 9)) * N4;
            *(float2*)&g_xp[r1 + col] = make_float2(acc[mi][nb][2] + bv.x,
                                                    acc[mi][nb][3] + bv.y);
        }
    }
}

// ==================== persistent recurrence (all 512 steps) =================
// 128 CTAs x 256 thr. CTA owns 32 n' rows. Wh (fp16 hi + lo*2048) resident in
// smem. Per step: stream h (single fp16) in 8 chunks of K=128 (4-stage, 3-ahead
// cp.async pipeline), 2-term HMMA, fused cell update. Step handoff via
// distributed per-CTA release/acquire flags (no atomics, no central barrier).
#define WROW2   2064                        // 1024 fp16 = 2048B + 16B pad
#define WLO_OFF (32 * WROW2)                // 66048
#define HOFF2   (2 * 32 * WROW2)            // 132096
#define HROW2   272                         // 128 fp16 = 256B + 16B pad
#define HSTG2   (64 * HROW2)                // 17408
#define DSOFF2  (HOFF2 + 4 * HSTG2)         // 201728
#define PCOFF2  (DSOFF2 + 32 * 68 * 4)      // 210432
#define PSMEM2  (PCOFF2 + 512 * 4)          // 212480

__global__ void __launch_bounds__(256, 1) lstm_persist()
{
    extern __shared__ __align__(128) char smem[];
    const uint32_t sb = smem_u32(smem);
    const int tid = threadIdx.x;
    const int cta = blockIdx.x;
    const int n0 = cta * 32;
    const int wid = tid >> 5, l = tid & 31;
    const int wm = wid & 1, wn = wid >> 1;    // 2 m-halves x 4 n-quarters

    // ---- load resident W slice (hi & scaled-lo fp16), 128 KB ----
    for (int i = tid; i < 4096; i += 256) {
        int row = i >> 7, c16 = i & 127;
        uint32_t d = sb + row * WROW2 + c16 * 16;
        CP16(d,           g_WhT_h + (size_t)(n0 + row) * HSZ + c16 * 8);
        CP16(d + WLO_OFF, g_WhT_l + (size_t)(n0 + row) * HSZ + c16 * 8);
    }
    CPCOMMIT(); CPWAIT0();

    float* c_s = (float*)(smem + PCOFF2);
    float* Ds  = (float*)(smem + DSOFF2);
    for (int i = tid; i < 512; i += 256) c_s[i] = 0.f;
    __syncthreads();

    const uint32_t aoffh = sb + (wm * 16 + (l & 15)) * WROW2 + (l >> 4) * 16;
    const uint32_t aoffl = aoffh + WLO_OFF;
    const uint32_t boffr = (wn * 16 + (l & 15)) * HROW2 + (l >> 4) * 16;

    const int b = tid & 63, q = tid >> 6;     // cell ownership: (b, hc=2q, 2q+1)
    const int hcg0 = cta * 8 + 2 * q;

    for (int t = 0; t < SEQ; t++) {
        const __half* __restrict__ hin = g_h16[t & 1];

        // xp prefetch (independent of h_t) — overlaps flag-wait + fill
        const float* xprow = g_xp + ((size_t)t * BATCH + b) * N4 + n0 + q * 8;
        float4 xpA = *(const float4*)(xprow);
        float4 xpB = *(const float4*)(xprow + 4);

        // distributed flag barrier: wait until every CTA published h_t
        if (t > 0) {
            if (tid < NCTA) {
                unsigned f;
                do {
                    asm volatile("ld.global.acquire.gpu.u32 %0, [%1];"
                                 : "=r"(f) : "l"(g_flags + tid * 8) : "memory");
                } while (f < (unsigned)t);
            }
            __syncthreads();
        }

        auto load_h = [&](int c, int st) {
            uint32_t base = sb + HOFF2 + (uint32_t)st * HSTG2;
            int ko = c * 128;
#pragma unroll
            for (int j = 0; j < 4; j++) {
                int cid = tid * 4 + j;        // 0..1023
                int row = cid >> 4, kc = cid & 15;
                CP16(base + row * HROW2 + kc * 16, hin + (size_t)row * HSZ + ko + kc * 8);
            }
            CPCOMMIT();
        };

        float accH[2][4], accL[2][4];
#pragma unroll
        for (int i = 0; i < 2; i++)
#pragma unroll
            for (int k = 0; k < 4; k++) { accH[i][k] = 0.f; accL[i][k] = 0.f; }

        load_h(0, 0);
        load_h(1, 1);
        load_h(2, 2);

#pragma unroll 1
        for (int c = 0; c < 8; c++) {
            if (c <= 5) { CPWAIT2(); } else if (c == 6) { CPWAIT1(); } else { CPWAIT0(); }
            __syncthreads();                      // data ready; prev chunk fully consumed
            if (c + 3 < 8) load_h(c + 3, (c + 3) & 3);
            uint32_t wbase = c * 256;             // byte offset into W row (K-major)
            uint32_t hb = sb + HOFF2 + (uint32_t)(c & 3) * HSTG2 + boffr;
#pragma unroll
            for (int ks = 0; ks < 8; ks++) {
                uint32_t ah[4], al[4], bh[4];
                ldm4(aoffh + wbase + ks * 32, ah);
                ldm4(aoffl + wbase + ks * 32, al);
                ldm4(hb + ks * 32, bh);
                hmma_f16(accH[0], ah, bh[0], bh[2]);
                hmma_f16(accH[1], ah, bh[1], bh[3]);
                hmma_f16(accL[0], al, bh[0], bh[2]);
                hmma_f16(accL[1], al, bh[1], bh[3]);
            }
        }

        // D [32 n'][64 b] -> smem (combine lo term)
        {
            int r = wm * 16 + (l >> 2);
#pragma unroll
            for (int nb = 0; nb < 2; nb++) {
                int col = wn * 16 + nb * 8 + 2 * (l & 3);
                const float s = 1.0f / 2048.0f;
                Ds[r * 68 + col]           = accH[nb][0] + accL[nb][0] * s;
                Ds[r * 68 + col + 1]       = accH[nb][1] + accL[nb][1] * s;
                Ds[(r + 8) * 68 + col]     = accH[nb][2] + accL[nb][2] * s;
                Ds[(r + 8) * 68 + col + 1] = accH[nb][3] + accL[nb][3] * s;
            }
        }
        __syncthreads();

        // fused cell update: this thread owns (b, hc=2q) and (b, hc=2q+1)
        float hv[2];
#pragma unroll
        for (int j = 0; j < 2; j++) {
            int hcl = 2 * q + j;
            float iv = Ds[(hcl * 4 + 0) * 68 + b];
            float fv = Ds[(hcl * 4 + 1) * 68 + b];
            float gv = Ds[(hcl * 4 + 2) * 68 + b];
            float ov = Ds[(hcl * 4 + 3) * 68 + b];
            float xi = j ? xpB.x : xpA.x;
            float xf = j ? xpB.y : xpA.y;
            float xg = j ? xpB.z : xpA.z;
            float xo = j ? xpB.w : xpA.w;
            float ig = fsig(iv + xi);
            float fg = fsig(fv + xf);
            float gg = ftanh(gv + xg);
            float og = fsig(ov + xo);
            int ci = b * 8 + hcl;
            float cnew = c_s[ci] * fg + ig * gg;
            c_s[ci] = cnew;
            hv[j] = og * ftanh(cnew);
        }
        {
            int idx = b * HSZ + hcg0;
            *(__half2*)(g_h16[(t + 1) & 1] + idx) =
                __halves2half2(__float2half_rn(hv[0]), __float2half_rn(hv[1]));
            if (t == SEQ - 1) {
                *(float2*)(g_hf + idx) = make_float2(hv[0], hv[1]);
                *(float2*)(g_c  + idx) = make_float2(c_s[b * 8 + 2 * q], c_s[b * 8 + 2 * q + 1]);
            }
        }

        // publish h_{t+1}: CG-style release-arrive (bar.sync orders all threads'
        // h stores before tid0's release store)
        __syncthreads();
        if (tid == 0) {
            asm volatile("st.global.release.gpu.u32 [%0], %1;"
                         ::"l"(g_flags + cta * 8), "r"((unsigned)(t + 1)) : "memory");
        }
    }
}

// ============================== output ======================================
__global__ void copy_out_kernel(float* __restrict__ out, int n)
{
    int i = blockIdx.x * blockDim.x + threadIdx.x;
    if (i >= n) return;
    if (i < BATCH * HSZ)          out[i] = g_hf[i];
    else if (i < 2 * BATCH * HSZ) out[i] = g_c[i - BATCH * HSZ];
    else                          out[i] = 0.0f;
}

// ============================== launcher ====================================
extern "C" void kernel_launch(void* const* d_in, const int* in_sizes, int n_in,
                              void* d_out, int out_size)
{
    const float* x   = (const float*)d_in[0];
    const float* wii = (const float*)d_in[1];
    const float* bii = (const float*)d_in[2];
    const float* whi = (const float*)d_in[3];
    const float* bhi = (const float*)d_in[4];
    const float* wif = (const float*)d_in[5];
    const float* bif = (const float*)d_in[6];
    const float* whf = (const float*)d_in[7];
    const float* bhf = (const float*)d_in[8];
    const float* wig = (const float*)d_in[9];
    const float* big = (const float*)d_in[10];
    const float* whg = (const float*)d_in[11];
    const float* bhg = (const float*)d_in[12];
    const float* wio = (const float*)d_in[13];
    const float* bio = (const float*)d_in[14];
    const float* who = (const float*)d_in[15];
    const float* bho = (const float*)d_in[16];
    (void)in_sizes; (void)n_in;

    static int configured = 0;
    if (!configured) {
        cudaFuncSetAttribute(xproj_mma,    cudaFuncAttributeMaxDynamicSharedMemorySize, 3 * XSTG);
        cudaFuncSetAttribute(lstm_persist, cudaFuncAttributeMaxDynamicSharedMemorySize, PSMEM2);
        configured = 1;
    }

    pack_w<<<dim3(32, 32, 8), dim3(32, 8)>>>(wii, wif, wig, wio, whi, whf, whg, who);
    init_state<<<(BATCH * HSZ + 255) / 256, 256>>>(bii, bhi, bif, bhf, big, bhg, bio, bho);
    conv_x<<<(MTOT * HSZ / 4 + 255) / 256, 256>>>(x);

    xproj_mma<<<dim3(32, 256), 256, 3 * XSTG>>>();

    lstm_persist<<<NCTA, 256, PSMEM2>>>();

    copy_out_kernel<<<(out_size + 255) / 256, 256>>>((float*)d_out, out_size);
}